// round 4
// baseline (speedup 1.0000x reference)
#include <cuda_runtime.h>
#include <cstddef>

typedef unsigned long long ull;

#define NTHREADS 256
#define TROWS 64

// ---------------- packed fp32x2 helpers ----------------
__device__ __forceinline__ ull ffma2(ull a, ull b, ull c) {
    ull d; asm("fma.rn.f32x2 %0, %1, %2, %3;" : "=l"(d) : "l"(a), "l"(b), "l"(c)); return d;
}
__device__ __forceinline__ ull addf2(ull a, ull b) {
    ull d; asm("add.rn.f32x2 %0, %1, %2;" : "=l"(d) : "l"(a), "l"(b)); return d;
}
__device__ __forceinline__ ull dup2(float x) {
    ull d; asm("mov.b64 %0, {%1, %1};" : "=l"(d) : "f"(x)); return d;
}
__device__ __forceinline__ float2 u2f(ull a) {
    float2 f; asm("mov.b64 {%0, %1}, %2;" : "=f"(f.x), "=f"(f.y) : "l"(a)); return f;
}
__device__ __forceinline__ float lrelu(float v) { return v > 0.0f ? v : 0.01f * v; }

// ---------------- epilogue chunk maps ----------------
__constant__ int c_kind[31] = {0,0,0,0,0,0,0,0,0,0,0,0,1,1,1,1,0,0,0,1,0,0,0,0,0,1,1,1,1,1,1};
__constant__ int c_A[31]    = {320,152,304,304,304,304,304,152,152,152,152,152,
                               40,41,42,43, 152,208,416, 39, 208,152,416,360,152,
                               44,45,46,47,48,49};
__constant__ int c_B[31]    = {18,20,22,23,24,25,26,27,28,29,30,31,
                               0,2,3,5, 35,36,37, 1, 32,33,34,19,38,
                               4,4,4,4,4,4};
// blob: suit@0(40) rank@40(112) pos@152(56) action@208(96) active@304(16)
//       street@320(40) numpl@360(56) blind@416(16)

// ---------------- shared layout (floats) ----------------
#define OFF_SS    0                   // 64*52 = 3328
#define OFF_BLOB  3328                // 432
#define OFF_SW    3760                // 48
#define OFF_SB    3808                // 48
#define OFF_BIAS  3856                // 704
#define OFF_A     4560                // 6144  (stride 96)
#define OFF_B     10704               // 6144  (stride 96); A..B = D region (stride 160)
#define OFF_C     16848               // 10240 (stride 160)
#define OFF_W     27088               // 10368 weight staging
#define SMEM_FLOATS 37456
#define SMEM_BYTES  (SMEM_FLOATS * 4)  // 149824

// swizzled address of logical (row, k) in a buffer with row stride `stride` (mult of 32)
__device__ __forceinline__ int swaddr(int r, int k, int stride) {
    int k4 = k >> 2, s = (r >> 1) & 7;
    return r * stride + ((((k4 & ~7) | ((k4 ^ s) & 7)) << 2) | (k & 3));
}

// ---------------- dense layer ----------------
// Xs[rows=64][SIN swizzled] -> Ys[rows=64][SOUT swizzled, at k-offset KOFF]
// thread: rows (2L, 2L+1), cols wg*8 + jj*64; weights staged to Wbuf per K-chunk.
template<int NIN, int SIN, int NOUT, int SOUT, int KCHUNK, bool ACT, int KOFF>
__device__ __forceinline__ void layer(const float* __restrict__ Xs, float* __restrict__ Ys,
                                      const float* __restrict__ Wg, const float* __restrict__ bsm,
                                      float* __restrict__ Wbuf)
{
    const int t   = threadIdx.x;
    const int L   = t & 31;
    const int wg  = t >> 5;
    const int r0  = L << 1;
    const int swz = L & 7;
    constexpr int NJB = (NOUT + 63) >> 6;

    ull acc[NJB][2][4];
    #pragma unroll
    for (int a = 0; a < NJB; a++)
        #pragma unroll
        for (int b = 0; b < 2; b++)
            #pragma unroll
            for (int c = 0; c < 4; c++) acc[a][b][c] = 0ull;

    const float* x0p = Xs + r0 * SIN;
    const float* x1p = Xs + (r0 + 1) * SIN;

    for (int kc = 0; kc < NIN; kc += KCHUNK) {
        __syncthreads();  // Wbuf WAR + prev stores visible
        for (int i = t * 4; i < KCHUNK * NOUT; i += NTHREADS * 4)
            *reinterpret_cast<float4*>(Wbuf + i) =
                *reinterpret_cast<const float4*>(Wg + kc * NOUT + i);
        __syncthreads();

        #pragma unroll 2
        for (int k = 0; k < KCHUNK; k += 4) {
            int k4 = (kc + k) >> 2;
            int kw = ((k4 & ~7) | ((k4 ^ swz) & 7)) << 2;
            float4 xa = *reinterpret_cast<const float4*>(x0p + kw);
            float4 xb = *reinterpret_cast<const float4*>(x1p + kw);
            const float* wr = Wbuf + k * NOUT;
            #pragma unroll
            for (int dk = 0; dk < 4; dk++) {
                ull xd0 = dup2(reinterpret_cast<const float*>(&xa)[dk]);
                ull xd1 = dup2(reinterpret_cast<const float*>(&xb)[dk]);
                #pragma unroll
                for (int jj = 0; jj < NJB; jj++) {
                    int jb = (wg << 3) + (jj << 6);
                    if (jb < NOUT) {
                        const float* wp = wr + dk * NOUT + jb;
                        ulonglong2 wA = *reinterpret_cast<const ulonglong2*>(wp);
                        ulonglong2 wB = *reinterpret_cast<const ulonglong2*>(wp + 4);
                        acc[jj][0][0] = ffma2(xd0, wA.x, acc[jj][0][0]);
                        acc[jj][0][1] = ffma2(xd0, wA.y, acc[jj][0][1]);
                        acc[jj][0][2] = ffma2(xd0, wB.x, acc[jj][0][2]);
                        acc[jj][0][3] = ffma2(xd0, wB.y, acc[jj][0][3]);
                        acc[jj][1][0] = ffma2(xd1, wA.x, acc[jj][1][0]);
                        acc[jj][1][1] = ffma2(xd1, wA.y, acc[jj][1][1]);
                        acc[jj][1][2] = ffma2(xd1, wB.x, acc[jj][1][2]);
                        acc[jj][1][3] = ffma2(xd1, wB.y, acc[jj][1][3]);
                    }
                }
            }
        }
    }

    // epilogue: bias + act + swizzled store
    #pragma unroll
    for (int jj = 0; jj < NJB; jj++) {
        int jb = (wg << 3) + (jj << 6);
        if (jb < NOUT) {
            ulonglong2 bA = *reinterpret_cast<const ulonglong2*>(bsm + jb);
            ulonglong2 bB = *reinterpret_cast<const ulonglong2*>(bsm + jb + 4);
            ull bp[4] = {bA.x, bA.y, bB.x, bB.y};
            int j4a = (KOFF + jb) >> 2;
            int wa  = ((j4a & ~7) | ((j4a ^ swz) & 7)) << 2;
            int j4b = j4a + 1;
            int wb2 = ((j4b & ~7) | ((j4b ^ swz) & 7)) << 2;
            #pragma unroll
            for (int row = 0; row < 2; row++) {
                float o[8];
                #pragma unroll
                for (int cp = 0; cp < 4; cp++) {
                    float2 v = u2f(addf2(acc[jj][row][cp], bp[cp]));
                    if (ACT) { v.x = lrelu(v.x); v.y = lrelu(v.y); }
                    o[cp * 2] = v.x; o[cp * 2 + 1] = v.y;
                }
                float* yr = Ys + (r0 + row) * SOUT;
                *reinterpret_cast<float4*>(yr + wa)  = make_float4(o[0], o[1], o[2], o[3]);
                *reinterpret_cast<float4*>(yr + wb2) = make_float4(o[4], o[5], o[6], o[7]);
            }
        }
    }
}

// final 64->64 layer, no activation, direct global store to out cols [0,64)
__device__ __forceinline__ void layer_final(const float* __restrict__ Xs,
                                            const float* __restrict__ Wg,
                                            const float* __restrict__ bsm,
                                            float* __restrict__ Wbuf,
                                            float* __restrict__ out, size_t g0)
{
    const int t   = threadIdx.x;
    const int L   = t & 31;
    const int wg  = t >> 5;
    const int r0  = L << 1;
    const int swz = L & 7;

    ull acc[2][4];
    #pragma unroll
    for (int b = 0; b < 2; b++)
        #pragma unroll
        for (int c = 0; c < 4; c++) acc[b][c] = 0ull;

    const float* x0p = Xs + r0 * 96;
    const float* x1p = Xs + (r0 + 1) * 96;

    __syncthreads();
    for (int i = t * 4; i < 64 * 64; i += NTHREADS * 4)
        *reinterpret_cast<float4*>(Wbuf + i) = *reinterpret_cast<const float4*>(Wg + i);
    __syncthreads();

    const int jb = wg << 3;
    #pragma unroll 2
    for (int k = 0; k < 64; k += 4) {
        int k4 = k >> 2;
        int kw = ((k4 & ~7) | ((k4 ^ swz) & 7)) << 2;
        float4 xa = *reinterpret_cast<const float4*>(x0p + kw);
        float4 xb = *reinterpret_cast<const float4*>(x1p + kw);
        const float* wr = Wbuf + k * 64 + jb;
        #pragma unroll
        for (int dk = 0; dk < 4; dk++) {
            ull xd0 = dup2(reinterpret_cast<const float*>(&xa)[dk]);
            ull xd1 = dup2(reinterpret_cast<const float*>(&xb)[dk]);
            const float* wp = wr + dk * 64;
            ulonglong2 wA = *reinterpret_cast<const ulonglong2*>(wp);
            ulonglong2 wB = *reinterpret_cast<const ulonglong2*>(wp + 4);
            acc[0][0] = ffma2(xd0, wA.x, acc[0][0]);
            acc[0][1] = ffma2(xd0, wA.y, acc[0][1]);
            acc[0][2] = ffma2(xd0, wB.x, acc[0][2]);
            acc[0][3] = ffma2(xd0, wB.y, acc[0][3]);
            acc[1][0] = ffma2(xd1, wA.x, acc[1][0]);
            acc[1][1] = ffma2(xd1, wA.y, acc[1][1]);
            acc[1][2] = ffma2(xd1, wB.x, acc[1][2]);
            acc[1][3] = ffma2(xd1, wB.y, acc[1][3]);
        }
    }

    ulonglong2 bA = *reinterpret_cast<const ulonglong2*>(bsm + jb);
    ulonglong2 bB = *reinterpret_cast<const ulonglong2*>(bsm + jb + 4);
    ull bp[4] = {bA.x, bA.y, bB.x, bB.y};
    #pragma unroll
    for (int row = 0; row < 2; row++) {
        float o[8];
        #pragma unroll
        for (int cp = 0; cp < 4; cp++) {
            float2 v = u2f(addf2(acc[row][cp], bp[cp]));
            o[cp * 2] = v.x; o[cp * 2 + 1] = v.y;
        }
        float* op = out + (g0 + r0 + row) * 312 + jb;
        *reinterpret_cast<float4*>(op)     = make_float4(o[0], o[1], o[2], o[3]);
        *reinterpret_cast<float4*>(op + 4) = make_float4(o[4], o[5], o[6], o[7]);
    }
}

__global__ void __launch_bounds__(NTHREADS, 1)
preproc_kernel(const float* __restrict__ state,
               const float* __restrict__ suit_emb, const float* __restrict__ rank_emb,
               const float* __restrict__ hW1, const float* __restrict__ hb1,
               const float* __restrict__ hW2, const float* __restrict__ hb2,
               const float* __restrict__ hW3, const float* __restrict__ hb3,
               const float* __restrict__ bW1, const float* __restrict__ bb1,
               const float* __restrict__ bW2, const float* __restrict__ bb2,
               const float* __restrict__ bW3, const float* __restrict__ bb3,
               const float* __restrict__ cW1, const float* __restrict__ cb1,
               const float* __restrict__ cW2, const float* __restrict__ cb2,
               const float* __restrict__ cW3, const float* __restrict__ cb3,
               const float* __restrict__ pos_emb, const float* __restrict__ action_emb,
               const float* __restrict__ active_emb, const float* __restrict__ street_emb,
               const float* __restrict__ numpl_emb, const float* __restrict__ blind_emb,
               const float* __restrict__ scalar_W, const float* __restrict__ scalar_b,
               float* __restrict__ out)
{
    extern __shared__ float smem[];
    float* Ss   = smem + OFF_SS;
    float* blob = smem + OFF_BLOB;
    float* sW   = smem + OFF_SW;
    float* sB   = smem + OFF_SB;
    float* bias = smem + OFF_BIAS;
    float* A    = smem + OFF_A;     // stride 96
    float* Bb   = smem + OFF_B;     // stride 96
    float* D    = smem + OFF_A;     // stride 160 (overlays A+B)
    float* C    = smem + OFF_C;     // stride 160 (or 96 for c2 out)
    float* Wbuf = smem + OFF_W;

    const int t = threadIdx.x;
    const size_t g0 = (size_t)blockIdx.x * TROWS;

    // ---- state tile ----
    const float* sp = state + g0 * 50;
    for (int i = t; i < TROWS * 50; i += NTHREADS) {
        int r = i / 50, c = i - r * 50;
        Ss[r * 52 + c] = sp[i];
    }
    // ---- embedding tables + scalars + biases ----
    for (int i = t; i < 40;  i += NTHREADS) blob[0   + i] = suit_emb[i];
    for (int i = t; i < 112; i += NTHREADS) blob[40  + i] = rank_emb[i];
    for (int i = t; i < 56;  i += NTHREADS) blob[152 + i] = pos_emb[i];
    for (int i = t; i < 96;  i += NTHREADS) blob[208 + i] = action_emb[i];
    for (int i = t; i < 16;  i += NTHREADS) blob[304 + i] = active_emb[i];
    for (int i = t; i < 40;  i += NTHREADS) blob[320 + i] = street_emb[i];
    for (int i = t; i < 56;  i += NTHREADS) blob[360 + i] = numpl_emb[i];
    for (int i = t; i < 16;  i += NTHREADS) blob[416 + i] = blind_emb[i];
    for (int i = t; i < 48;  i += NTHREADS) { sW[i] = scalar_W[i]; sB[i] = scalar_b[i]; }
    for (int i = t; i < 64;  i += NTHREADS) bias[0   + i] = hb1[i];
    for (int i = t; i < 64;  i += NTHREADS) bias[64  + i] = hb2[i];
    for (int i = t; i < 64;  i += NTHREADS) bias[128 + i] = hb3[i];
    for (int i = t; i < 80;  i += NTHREADS) bias[192 + i] = bb1[i];
    for (int i = t; i < 80;  i += NTHREADS) bias[272 + i] = bb2[i];
    for (int i = t; i < 80;  i += NTHREADS) bias[352 + i] = bb3[i];
    for (int i = t; i < 144; i += NTHREADS) bias[432 + i] = cb1[i];
    for (int i = t; i < 64;  i += NTHREADS) bias[576 + i] = cb2[i];
    for (int i = t; i < 64;  i += NTHREADS) bias[640 + i] = cb3[i];
    __syncthreads();

    // ---- cheap output columns 64..311 ----
    for (int i = t; i < TROWS * 248; i += NTHREADS) {
        int r = i / 248, cc = i - r * 248;
        int ch = cc >> 3, e = cc & 7;
        int kind = c_kind[ch], Ai = c_A[ch], Bc = c_B[ch];
        float v;
        if (kind == 0) {
            int xi = (int)Ss[r * 52 + Bc];
            v = blob[Ai + xi * 8 + e];
        } else {
            v = Ss[r * 52 + Ai] * sW[Bc * 8 + e] + sB[Bc * 8 + e];
        }
        out[(g0 + r) * 312 + 64 + cc] = v;
    }

    // ---- gather hand input (64 feats) -> A (swizzled, stride 96) ----
    for (int i = t; i < 64 * TROWS; i += NTHREADS) {
        int r = i & 63, k = i >> 6;
        int c = k >> 4, w = k & 15;
        float v;
        if (w < 8) { int s  = (int)Ss[r * 52 + 2 * c + 1]; v = blob[0  + s * 8 + w]; }
        else       { int rk = (int)Ss[r * 52 + 2 * c];     v = blob[40 + rk * 8 + (w - 8)]; }
        A[swaddr(r, k, 96)] = v;
    }

    layer<64, 96, 64, 96,  64, true,  0>(A,  Bb, hW1, bias + 0,   Wbuf);
    layer<64, 96, 64, 96,  64, true,  0>(Bb, A,  hW2, bias + 64,  Wbuf);
    layer<64, 96, 64, 160, 64, false, 0>(A,  C,  hW3, bias + 128, Wbuf);  // hand -> C k[0,64)

    __syncthreads();  // h3 done reading A before board gather overwrites

    // ---- gather board input (80 feats) -> A ----
    for (int i = t; i < 80 * TROWS; i += NTHREADS) {
        int r = i & 63, k = i >> 6;
        int c = k >> 4, w = k & 15;
        float v;
        if (w < 8) { int s  = (int)Ss[r * 52 + 9 + 2 * c]; v = blob[0  + s * 8 + w]; }
        else       { int rk = (int)Ss[r * 52 + 8 + 2 * c]; v = blob[40 + rk * 8 + (w - 8)]; }
        A[swaddr(r, k, 96)] = v;
    }

    layer<80, 96, 80, 96,  80, true,  0 >(A,  Bb, bW1, bias + 192, Wbuf);
    layer<80, 96, 80, 96,  80, true,  0 >(Bb, A,  bW2, bias + 272, Wbuf);
    layer<80, 96, 80, 160, 80, false, 64>(A,  C,  bW3, bias + 352, Wbuf);  // board -> C k[64,144)

    // ---- combined MLP ----
    layer<144, 160, 144, 160, 72,  true, 0>(C, D, cW1, bias + 432, Wbuf);  // C -> D (overlays A+B)
    layer<144, 160, 64,  96,  144, true, 0>(D, C, cW2, bias + 576, Wbuf);  // D -> C (stride 96)
    layer_final(C, cW3, bias + 640, Wbuf, out, g0);
}

extern "C" void kernel_launch(void* const* d_in, const int* in_sizes, int n_in,
                              void* d_out, int out_size)
{
    (void)n_in; (void)out_size;
    cudaFuncSetAttribute(preproc_kernel, cudaFuncAttributeMaxDynamicSharedMemorySize, SMEM_BYTES);

    const int nrows = in_sizes[0] / 50;     // 262144
    const int grid  = nrows / TROWS;        // 4096

    preproc_kernel<<<grid, NTHREADS, SMEM_BYTES>>>(
        (const float*)d_in[0],
        (const float*)d_in[1],  (const float*)d_in[2],
        (const float*)d_in[3],  (const float*)d_in[4],
        (const float*)d_in[5],  (const float*)d_in[6],
        (const float*)d_in[7],  (const float*)d_in[8],
        (const float*)d_in[9],  (const float*)d_in[10],
        (const float*)d_in[11], (const float*)d_in[12],
        (const float*)d_in[13], (const float*)d_in[14],
        (const float*)d_in[15], (const float*)d_in[16],
        (const float*)d_in[17], (const float*)d_in[18],
        (const float*)d_in[19], (const float*)d_in[20],
        (const float*)d_in[21], (const float*)d_in[22],
        (const float*)d_in[23], (const float*)d_in[24],
        (const float*)d_in[25], (const float*)d_in[26],
        (const float*)d_in[27], (const float*)d_in[28],
        (float*)d_out);
}

// round 5
// speedup vs baseline: 1.8460x; 1.8460x over previous
#include <cuda_runtime.h>
#include <cstddef>

typedef unsigned long long ull;

#define NTHREADS 256
#define TROWS 64

// ---------------- packed fp32x2 helpers ----------------
__device__ __forceinline__ ull ffma2(ull a, ull b, ull c) {
    ull d; asm("fma.rn.f32x2 %0, %1, %2, %3;" : "=l"(d) : "l"(a), "l"(b), "l"(c)); return d;
}
__device__ __forceinline__ float2 u2f(ull a) {
    float2 f; asm("mov.b64 {%0, %1}, %2;" : "=f"(f.x), "=f"(f.y) : "l"(a)); return f;
}
__device__ __forceinline__ float lrelu(float v) { return v > 0.0f ? v : 0.01f * v; }

// ---------------- epilogue chunk maps ----------------
__constant__ int c_kind[31] = {0,0,0,0,0,0,0,0,0,0,0,0,1,1,1,1,0,0,0,1,0,0,0,0,0,1,1,1,1,1,1};
__constant__ int c_A[31]    = {320,152,304,304,304,304,304,152,152,152,152,152,
                               40,41,42,43, 152,208,416, 39, 208,152,416,360,152,
                               44,45,46,47,48,49};
__constant__ int c_B[31]    = {18,20,22,23,24,25,26,27,28,29,30,31,
                               0,2,3,5, 35,36,37, 1, 32,33,34,19,38,
                               4,4,4,4,4,4};
// blob: suit@0(40) rank@40(112) pos@152(56) action@208(96) active@304(16)
//       street@320(40) numpl@360(56) blind@416(16)

// ---------------- shared layout (floats) ----------------
#define OFF_BLOB 0                   // 432
#define OFF_SW   432                 // 48
#define OFF_SB   480                 // 48
#define OFF_BIAS 528                 // 704  (ends 1232)
#define OFF_A    1232                // 64*84  = 5376  (stride 84)
#define OFF_B    (OFF_A + 5376)      // 64*84  = 5376  (stride 84)
#define OFF_C    (OFF_B + 5376)      // 64*148 = 9472  (stride 148)
#define OFF_W    (OFF_C + 9472)      // 4352 weight-chunk staging (transposed)
#define SMEM_FLOATS (OFF_W + 4352)   // 25808
#define SMEM_BYTES  (SMEM_FLOATS * 4)  // 103232 -> 2 CTAs/SM
// D (144-wide c1 output, stride 148) overlays A+B (10752 >= 9472)

// ---------------- dense (sub-)layer ----------------
// Xs[row][k] stride SIN; computes cols [JGOFF, JGOFF+NJ) of Wg ([NIN][NOUTG] row-major);
// writes Ys[row][JOFF + j] stride SOUT. Warp w owns j-tile [w*NJ/8, ...). KC%8==0.
template<int NIN, int SIN, int NOUTG, int JGOFF, int NJ, int SOUT, int JOFF, int KC, bool ACT>
__device__ __forceinline__ void layer(const float* __restrict__ Xs, float* __restrict__ Ys,
                                      const float* __restrict__ Wg, const float* __restrict__ bsm,
                                      float* __restrict__ Wt)
{
    const int t = threadIdx.x, L = t & 31, wid = t >> 5;
    constexpr int TILEJ = NJ / 8;          // 8 or 10
    constexpr int WS = KC + 4;             // Wt row stride; (KC+4)%8==4 -> conflict-free
    const int j0 = wid * TILEJ;

    ull acc[TILEJ][2];
    #pragma unroll
    for (int j = 0; j < TILEJ; j++) { acc[j][0] = 0ull; acc[j][1] = 0ull; }

    const float* x0 = Xs + L * SIN;
    const float* x1 = Xs + (L + 32) * SIN;

    for (int kc = 0; kc < NIN; kc += KC) {
        __syncthreads();
        // stage transposed chunk Wt[j][k], k in [kc, kc+KC)
        for (int i = t; i < NJ * (KC / 4); i += NTHREADS) {
            int j = i % NJ;
            int k4 = (i / NJ) << 2;
            const float* wp = Wg + (size_t)(kc + k4) * NOUTG + JGOFF + j;
            float w0 = __ldg(wp);
            float w1 = __ldg(wp + NOUTG);
            float w2 = __ldg(wp + 2 * NOUTG);
            float w3 = __ldg(wp + 3 * NOUTG);
            *reinterpret_cast<float4*>(Wt + j * WS + k4) = make_float4(w0, w1, w2, w3);
        }
        __syncthreads();

        const float* xk0 = x0 + kc;
        const float* xk1 = x1 + kc;
        #pragma unroll 4
        for (int k = 0; k < KC; k += 4) {
            ulonglong2 xa = *reinterpret_cast<const ulonglong2*>(xk0 + k);
            ulonglong2 xb = *reinterpret_cast<const ulonglong2*>(xk1 + k);
            const float* wr = Wt + j0 * WS + k;
            #pragma unroll
            for (int j = 0; j < TILEJ; j++) {
                ulonglong2 wv = *reinterpret_cast<const ulonglong2*>(wr + j * WS);
                acc[j][0] = ffma2(xa.x, wv.x, acc[j][0]);
                acc[j][0] = ffma2(xa.y, wv.y, acc[j][0]);
                acc[j][1] = ffma2(xb.x, wv.x, acc[j][1]);
                acc[j][1] = ffma2(xb.y, wv.y, acc[j][1]);
            }
        }
    }

    // epilogue: horizontal add + bias (+act), STS.64 pairs (j0 always even)
    #pragma unroll
    for (int j = 0; j < TILEJ; j += 2) {
        float b0 = bsm[j0 + j], b1 = bsm[j0 + j + 1];
        #pragma unroll
        for (int r = 0; r < 2; r++) {
            float2 s0 = u2f(acc[j][r]);
            float2 s1 = u2f(acc[j + 1][r]);
            float v0 = s0.x + s0.y + b0;
            float v1 = s1.x + s1.y + b1;
            if (ACT) { v0 = lrelu(v0); v1 = lrelu(v1); }
            *reinterpret_cast<float2*>(Ys + (L + 32 * r) * SOUT + JOFF + j0 + j) =
                make_float2(v0, v1);
        }
    }
}

// final 64->64 layer: no activation, direct global stores to out cols [0,64)
__device__ __forceinline__ void layer_final(const float* __restrict__ Xs,
                                            const float* __restrict__ Wg,
                                            const float* __restrict__ bsm,
                                            float* __restrict__ Wt,
                                            float* __restrict__ out, size_t g0)
{
    const int t = threadIdx.x, L = t & 31, wid = t >> 5;
    constexpr int WS = 68;
    const int j0 = wid * 8;

    ull acc[8][2];
    #pragma unroll
    for (int j = 0; j < 8; j++) { acc[j][0] = 0ull; acc[j][1] = 0ull; }

    __syncthreads();
    for (int i = t; i < 64 * 16; i += NTHREADS) {
        int j = i & 63;
        int k4 = (i >> 6) << 2;
        const float* wp = Wg + (size_t)k4 * 64 + j;
        *reinterpret_cast<float4*>(Wt + j * WS + k4) =
            make_float4(__ldg(wp), __ldg(wp + 64), __ldg(wp + 128), __ldg(wp + 192));
    }
    __syncthreads();

    const float* x0 = Xs + L * 148;
    const float* x1 = Xs + (L + 32) * 148;
    #pragma unroll 4
    for (int k = 0; k < 64; k += 4) {
        ulonglong2 xa = *reinterpret_cast<const ulonglong2*>(x0 + k);
        ulonglong2 xb = *reinterpret_cast<const ulonglong2*>(x1 + k);
        const float* wr = Wt + j0 * WS + k;
        #pragma unroll
        for (int j = 0; j < 8; j++) {
            ulonglong2 wv = *reinterpret_cast<const ulonglong2*>(wr + j * WS);
            acc[j][0] = ffma2(xa.x, wv.x, acc[j][0]);
            acc[j][0] = ffma2(xa.y, wv.y, acc[j][0]);
            acc[j][1] = ffma2(xb.x, wv.x, acc[j][1]);
            acc[j][1] = ffma2(xb.y, wv.y, acc[j][1]);
        }
    }

    #pragma unroll
    for (int r = 0; r < 2; r++) {
        float v[8];
        #pragma unroll
        for (int j = 0; j < 8; j++) {
            float2 s = u2f(acc[j][r]);
            v[j] = s.x + s.y + bsm[j0 + j];
        }
        float* op = out + (g0 + L + 32 * r) * 312 + j0;
        *reinterpret_cast<float4*>(op)     = make_float4(v[0], v[1], v[2], v[3]);
        *reinterpret_cast<float4*>(op + 4) = make_float4(v[4], v[5], v[6], v[7]);
    }
}

__global__ void __launch_bounds__(NTHREADS, 2)
preproc_kernel(const float* __restrict__ state,
               const float* __restrict__ suit_emb, const float* __restrict__ rank_emb,
               const float* __restrict__ hW1, const float* __restrict__ hb1,
               const float* __restrict__ hW2, const float* __restrict__ hb2,
               const float* __restrict__ hW3, const float* __restrict__ hb3,
               const float* __restrict__ bW1, const float* __restrict__ bb1,
               const float* __restrict__ bW2, const float* __restrict__ bb2,
               const float* __restrict__ bW3, const float* __restrict__ bb3,
               const float* __restrict__ cW1, const float* __restrict__ cb1,
               const float* __restrict__ cW2, const float* __restrict__ cb2,
               const float* __restrict__ cW3, const float* __restrict__ cb3,
               const float* __restrict__ pos_emb, const float* __restrict__ action_emb,
               const float* __restrict__ active_emb, const float* __restrict__ street_emb,
               const float* __restrict__ numpl_emb, const float* __restrict__ blind_emb,
               const float* __restrict__ scalar_W, const float* __restrict__ scalar_b,
               float* __restrict__ out)
{
    extern __shared__ float smem[];
    float* blob = smem + OFF_BLOB;
    float* sW   = smem + OFF_SW;
    float* sB   = smem + OFF_SB;
    float* bias = smem + OFF_BIAS;
    float* A    = smem + OFF_A;      // stride 84
    float* Bb   = smem + OFF_B;      // stride 84
    float* C    = smem + OFF_C;      // stride 148
    float* D    = smem + OFF_A;      // stride 148 (overlays A+B)
    float* Wt   = smem + OFF_W;

    const int t = threadIdx.x;
    const size_t g0 = (size_t)blockIdx.x * TROWS;
    const float* st = state + g0 * 50;

    // ---- stage tables + biases ----
    for (int i = t; i < 40;  i += NTHREADS) blob[0   + i] = suit_emb[i];
    for (int i = t; i < 112; i += NTHREADS) blob[40  + i] = rank_emb[i];
    for (int i = t; i < 56;  i += NTHREADS) blob[152 + i] = pos_emb[i];
    for (int i = t; i < 96;  i += NTHREADS) blob[208 + i] = action_emb[i];
    for (int i = t; i < 16;  i += NTHREADS) blob[304 + i] = active_emb[i];
    for (int i = t; i < 40;  i += NTHREADS) blob[320 + i] = street_emb[i];
    for (int i = t; i < 56;  i += NTHREADS) blob[360 + i] = numpl_emb[i];
    for (int i = t; i < 16;  i += NTHREADS) blob[416 + i] = blind_emb[i];
    for (int i = t; i < 48;  i += NTHREADS) { sW[i] = scalar_W[i]; sB[i] = scalar_b[i]; }
    for (int i = t; i < 64;  i += NTHREADS) bias[0   + i] = hb1[i];
    for (int i = t; i < 64;  i += NTHREADS) bias[64  + i] = hb2[i];
    for (int i = t; i < 64;  i += NTHREADS) bias[128 + i] = hb3[i];
    for (int i = t; i < 80;  i += NTHREADS) bias[192 + i] = bb1[i];
    for (int i = t; i < 80;  i += NTHREADS) bias[272 + i] = bb2[i];
    for (int i = t; i < 80;  i += NTHREADS) bias[352 + i] = bb3[i];
    for (int i = t; i < 144; i += NTHREADS) bias[432 + i] = cb1[i];
    for (int i = t; i < 64;  i += NTHREADS) bias[576 + i] = cb2[i];
    for (int i = t; i < 64;  i += NTHREADS) bias[640 + i] = cb3[i];
    __syncthreads();

    // ---- cheap output columns 64..311 (state read straight from global/L1) ----
    for (int i = t; i < TROWS * 248; i += NTHREADS) {
        int r = i / 248, cc = i - r * 248;
        int ch = cc >> 3, e = cc & 7;
        int kind = c_kind[ch], Ai = c_A[ch], Bc = c_B[ch];
        float v;
        if (kind == 0) {
            int xi = (int)__ldg(st + r * 50 + Bc);
            v = blob[Ai + xi * 8 + e];
        } else {
            v = __ldg(st + r * 50 + Ai) * sW[Bc * 8 + e] + sB[Bc * 8 + e];
        }
        out[(g0 + r) * 312 + 64 + cc] = v;
    }

    // ---- gather hand input (64 feats) -> A row-major ----
    for (int i = t; i < 64 * TROWS; i += NTHREADS) {
        int r = i & 63, k = i >> 6;
        int c = k >> 4, w = k & 15;
        float v;
        if (w < 8) { int s  = (int)__ldg(st + r * 50 + 2 * c + 1); v = blob[0  + s * 8 + w]; }
        else       { int rk = (int)__ldg(st + r * 50 + 2 * c);     v = blob[40 + rk * 8 + (w - 8)]; }
        A[r * 84 + k] = v;
    }
    // (h1's staging __syncthreads establishes visibility)

    layer<64, 84, 64, 0, 64, 84, 0, 64, true >(A,  Bb, hW1, bias + 0,   Wt);
    layer<64, 84, 64, 0, 64, 84, 0, 64, true >(Bb, A,  hW2, bias + 64,  Wt);
    layer<64, 84, 64, 0, 64, 148, 0, 64, false>(A, C,  hW3, bias + 128, Wt);  // -> C[:,0:64)

    __syncthreads();  // h3 finished reading A before board gather overwrites

    // ---- gather board input (80 feats) -> A ----
    for (int i = t; i < 80 * TROWS; i += NTHREADS) {
        int r = i & 63, k = i >> 6;
        int c = k >> 4, w = k & 15;
        float v;
        if (w < 8) { int s  = (int)__ldg(st + r * 50 + 9 + 2 * c); v = blob[0  + s * 8 + w]; }
        else       { int rk = (int)__ldg(st + r * 50 + 8 + 2 * c); v = blob[40 + rk * 8 + (w - 8)]; }
        A[r * 84 + k] = v;
    }

    layer<80, 84, 80, 0, 80, 84, 0, 40, true >(A,  Bb, bW1, bias + 192, Wt);
    layer<80, 84, 80, 0, 80, 84, 0, 40, true >(Bb, A,  bW2, bias + 272, Wt);
    layer<80, 84, 80, 0, 80, 148, 64, 40, false>(A, C, bW3, bias + 352, Wt);  // -> C[:,64:144)

    // ---- combined MLP: C[144] -> D[144] -> C[0:64) -> out ----
    layer<144, 148, 144, 0,  80, 148, 0,  48, true>(C, D, cW1, bias + 432, Wt);      // c1a
    layer<144, 148, 144, 80, 64, 148, 80, 48, true>(C, D, cW1, bias + 432 + 80, Wt); // c1b
    layer<144, 148, 64,  0,  64, 148, 0,  48, true>(D, C, cW2, bias + 576, Wt);      // c2
    layer_final(C, cW3, bias + 640, Wt, out, g0);
}

extern "C" void kernel_launch(void* const* d_in, const int* in_sizes, int n_in,
                              void* d_out, int out_size)
{
    (void)n_in; (void)out_size;
    cudaFuncSetAttribute(preproc_kernel, cudaFuncAttributeMaxDynamicSharedMemorySize, SMEM_BYTES);

    const int nrows = in_sizes[0] / 50;     // 262144
    const int grid  = nrows / TROWS;        // 4096

    preproc_kernel<<<grid, NTHREADS, SMEM_BYTES>>>(
        (const float*)d_in[0],
        (const float*)d_in[1],  (const float*)d_in[2],
        (const float*)d_in[3],  (const float*)d_in[4],
        (const float*)d_in[5],  (const float*)d_in[6],
        (const float*)d_in[7],  (const float*)d_in[8],
        (const float*)d_in[9],  (const float*)d_in[10],
        (const float*)d_in[11], (const float*)d_in[12],
        (const float*)d_in[13], (const float*)d_in[14],
        (const float*)d_in[15], (const float*)d_in[16],
        (const float*)d_in[17], (const float*)d_in[18],
        (const float*)d_in[19], (const float*)d_in[20],
        (const float*)d_in[21], (const float*)d_in[22],
        (const float*)d_in[23], (const float*)d_in[24],
        (const float*)d_in[25], (const float*)d_in[26],
        (const float*)d_in[27], (const float*)d_in[28],
        (float*)d_out);
}

// round 6
// speedup vs baseline: 2.0372x; 1.1036x over previous
#include <cuda_runtime.h>
#include <cstddef>

typedef unsigned long long ull;

#define NTHREADS 256
#define TROWS 64

// ======== transposed-weight global scratch: Wt[j][k] per layer ========
__device__ __align__(16) float g_wt[65536];
// segment prefix (same for src and dst), NIN, NOUT per segment
__constant__ int c_pre[10]  = {0,4096,8192,12288,18688,25088,31488,52224,61440,65536};
__constant__ int c_nin[9]   = {64,64,64,80,80,80,144,144,64};
__constant__ int c_nout[9]  = {64,64,64,80,80,80,144,64,64};

__global__ void prep_kernel(const float* w0,const float* w1,const float* w2,
                            const float* w3,const float* w4,const float* w5,
                            const float* w6,const float* w7,const float* w8)
{
    const float* W[9] = {w0,w1,w2,w3,w4,w5,w6,w7,w8};
    int i = blockIdx.x * blockDim.x + threadIdx.x;
    if (i >= 65536) return;
    int s = 0;
    while (i >= c_pre[s + 1]) s++;
    int l = i - c_pre[s];
    int nin = c_nin[s], nout = c_nout[s];
    int j = l / nin, k = l - j * nin;
    g_wt[i] = W[s][k * nout + j];
}

// ======== packed fp32x2 + cp.async helpers ========
__device__ __forceinline__ ull ffma2(ull a, ull b, ull c) {
    ull d; asm("fma.rn.f32x2 %0, %1, %2, %3;" : "=l"(d) : "l"(a), "l"(b), "l"(c)); return d;
}
__device__ __forceinline__ float2 u2f(ull a) {
    float2 f; asm("mov.b64 {%0, %1}, %2;" : "=f"(f.x), "=f"(f.y) : "l"(a)); return f;
}
__device__ __forceinline__ float lrelu(float v) { return v > 0.0f ? v : 0.01f * v; }
__device__ __forceinline__ void cpa16(float* dst, const float* src) {
    unsigned sa = (unsigned)__cvta_generic_to_shared(dst);
    asm volatile("cp.async.cg.shared.global [%0], [%1], 16;" :: "r"(sa), "l"(src));
}
#define CPA_COMMIT() asm volatile("cp.async.commit_group;" ::: "memory")
#define CPA_WAIT0()  asm volatile("cp.async.wait_group 0;"  ::: "memory")

// ======== epilogue chunk maps ========
__constant__ int c_kind[31] = {0,0,0,0,0,0,0,0,0,0,0,0,1,1,1,1,0,0,0,1,0,0,0,0,0,1,1,1,1,1,1};
__constant__ int c_A[31]    = {320,152,304,304,304,304,304,152,152,152,152,152,
                               40,41,42,43, 152,208,416, 39, 208,152,416,360,152,
                               44,45,46,47,48,49};
__constant__ int c_B[31]    = {18,20,22,23,24,25,26,27,28,29,30,31,
                               0,2,3,5, 35,36,37, 1, 32,33,34,19,38,
                               4,4,4,4,4,4};
// blob: suit@0(40) rank@40(112) pos@152(56) action@208(96) active@304(16)
//       street@320(40) numpl@360(56) blind@416(16)

// ======== shared layout (floats) ========
#define OFF_BLOB 0                   // 432
#define OFF_SW   432                 // 48
#define OFF_SB   480                 // 48
#define OFF_BIAS 528                 // 704 (ends 1232)
#define OFF_A    1232                // 64*84 = 5376 (stride 84)
#define OFF_B    6608                // 64*84 = 5376
#define OFF_C    11984               // 64*148 = 9472 (stride 148)
#define OFF_W    21456               // 2 slots * 3584
#define SLOTF    3584
#define SMEM_FLOATS 28624
#define SMEM_BYTES  (SMEM_FLOATS * 4)  // 114496 -> 2 CTAs/SM
// D (144-wide, stride 148) overlays A+B (10752 >= 9472)

// ======== dense (sub-)layer, cp.async double-buffered weights ========
// Xs[row][k] stride SIN; Wtg = transposed weights [NJ][NIN] row-major;
// writes Ys[row][JOFF+j] stride SOUT. Warp w owns j-tile of NJ/8 cols.
template<int NIN, int SIN, int NJ, int SOUT, int JOFF, int KC, bool ACT>
__device__ __forceinline__ void layer(const float* __restrict__ Xs, float* __restrict__ Ys,
                                      const float* __restrict__ Wtg,
                                      const float* __restrict__ bsm,
                                      float* __restrict__ Wslots)
{
    const int t = threadIdx.x, L = t & 31, wid = t >> 5;
    constexpr int TILEJ = NJ / 8;
    constexpr int WS  = KC + 4;
    constexpr int NCH = NIN / KC;
    constexpr int PER = KC / 4;
    const int j0 = wid * TILEJ;

    ull acc[TILEJ][2];
    #pragma unroll
    for (int j = 0; j < TILEJ; j++) { acc[j][0] = 0ull; acc[j][1] = 0ull; }

    const float* x0 = Xs + L * SIN;
    const float* x1 = Xs + (L + 32) * SIN;

    // ---- stage chunk 0 ----
    {
        float* dst = Wslots;
        const float* src = Wtg;
        for (int i = t; i < NJ * PER; i += NTHREADS) {
            int j = i / PER, k4 = (i - j * PER) << 2;
            cpa16(dst + j * WS + k4, src + j * NIN + k4);
        }
        CPA_COMMIT(); CPA_WAIT0();
    }
    __syncthreads();

    #pragma unroll
    for (int c = 0; c < NCH; c++) {
        if (c + 1 < NCH) {  // stage next chunk into other slot (overlapped)
            float* dst = Wslots + ((c + 1) & 1) * SLOTF;
            const float* src = Wtg + (c + 1) * KC;
            for (int i = t; i < NJ * PER; i += NTHREADS) {
                int j = i / PER, k4 = (i - j * PER) << 2;
                cpa16(dst + j * WS + k4, src + j * NIN + k4);
            }
            CPA_COMMIT();
        }
        // ---- compute chunk c ----
        {
            const float* Wt = Wslots + (c & 1) * SLOTF;
            const float* xk0 = x0 + c * KC;
            const float* xk1 = x1 + c * KC;
            const float* wr0 = Wt + j0 * WS;
            #pragma unroll 4
            for (int k = 0; k < KC; k += 4) {
                ulonglong2 xa = *reinterpret_cast<const ulonglong2*>(xk0 + k);
                ulonglong2 xb = *reinterpret_cast<const ulonglong2*>(xk1 + k);
                const float* wr = wr0 + k;
                #pragma unroll
                for (int j = 0; j < TILEJ; j++) {
                    ulonglong2 wv = *reinterpret_cast<const ulonglong2*>(wr + j * WS);
                    acc[j][0] = ffma2(xa.x, wv.x, acc[j][0]);
                    acc[j][0] = ffma2(xa.y, wv.y, acc[j][0]);
                    acc[j][1] = ffma2(xb.x, wv.x, acc[j][1]);
                    acc[j][1] = ffma2(xb.y, wv.y, acc[j][1]);
                }
            }
        }
        if (c + 1 < NCH) CPA_WAIT0();
        __syncthreads();
    }

    // ---- epilogue: horizontal add + bias (+act) ----
    #pragma unroll
    for (int j = 0; j < TILEJ; j += 2) {
        float b0 = bsm[j0 + j], b1 = bsm[j0 + j + 1];
        #pragma unroll
        for (int r = 0; r < 2; r++) {
            float2 s0 = u2f(acc[j][r]);
            float2 s1 = u2f(acc[j + 1][r]);
            float v0 = s0.x + s0.y + b0;
            float v1 = s1.x + s1.y + b1;
            if (ACT) { v0 = lrelu(v0); v1 = lrelu(v1); }
            *reinterpret_cast<float2*>(Ys + (L + 32 * r) * SOUT + JOFF + j0 + j) =
                make_float2(v0, v1);
        }
    }
}

// final 64->64 layer: no activation, writes out cols [0,64)
__device__ __forceinline__ void layer_final(const float* __restrict__ Xs,
                                            const float* __restrict__ Wtg,
                                            const float* __restrict__ bsm,
                                            float* __restrict__ Wslots,
                                            float* __restrict__ out, size_t g0)
{
    const int t = threadIdx.x, L = t & 31, wid = t >> 5;
    constexpr int KC = 32, WS = 36, NCH = 2, PER = 8;
    const int j0 = wid * 8;

    ull acc[8][2];
    #pragma unroll
    for (int j = 0; j < 8; j++) { acc[j][0] = 0ull; acc[j][1] = 0ull; }

    const float* x0 = Xs + L * 148;
    const float* x1 = Xs + (L + 32) * 148;

    {
        for (int i = t; i < 64 * PER; i += NTHREADS) {
            int j = i / PER, k4 = (i - j * PER) << 2;
            cpa16(Wslots + j * WS + k4, Wtg + j * 64 + k4);
        }
        CPA_COMMIT(); CPA_WAIT0();
    }
    __syncthreads();

    #pragma unroll
    for (int c = 0; c < NCH; c++) {
        if (c + 1 < NCH) {
            float* dst = Wslots + SLOTF;
            const float* src = Wtg + KC;
            for (int i = t; i < 64 * PER; i += NTHREADS) {
                int j = i / PER, k4 = (i - j * PER) << 2;
                cpa16(dst + j * WS + k4, src + j * 64 + k4);
            }
            CPA_COMMIT();
        }
        {
            const float* Wt = Wslots + (c & 1) * SLOTF;
            const float* xk0 = x0 + c * KC;
            const float* xk1 = x1 + c * KC;
            const float* wr0 = Wt + j0 * WS;
            #pragma unroll 4
            for (int k = 0; k < KC; k += 4) {
                ulonglong2 xa = *reinterpret_cast<const ulonglong2*>(xk0 + k);
                ulonglong2 xb = *reinterpret_cast<const ulonglong2*>(xk1 + k);
                const float* wr = wr0 + k;
                #pragma unroll
                for (int j = 0; j < 8; j++) {
                    ulonglong2 wv = *reinterpret_cast<const ulonglong2*>(wr + j * WS);
                    acc[j][0] = ffma2(xa.x, wv.x, acc[j][0]);
                    acc[j][0] = ffma2(xa.y, wv.y, acc[j][0]);
                    acc[j][1] = ffma2(xb.x, wv.x, acc[j][1]);
                    acc[j][1] = ffma2(xb.y, wv.y, acc[j][1]);
                }
            }
        }
        if (c + 1 < NCH) CPA_WAIT0();
        __syncthreads();
    }

    #pragma unroll
    for (int r = 0; r < 2; r++) {
        float v[8];
        #pragma unroll
        for (int j = 0; j < 8; j++) {
            float2 s = u2f(acc[j][r]);
            v[j] = s.x + s.y + bsm[j0 + j];
        }
        float* op = out + (g0 + L + 32 * r) * 312 + j0;
        *reinterpret_cast<float4*>(op)     = make_float4(v[0], v[1], v[2], v[3]);
        *reinterpret_cast<float4*>(op + 4) = make_float4(v[4], v[5], v[6], v[7]);
    }
}

__global__ void __launch_bounds__(NTHREADS, 2)
preproc_kernel(const float* __restrict__ state,
               const float* __restrict__ suit_emb, const float* __restrict__ rank_emb,
               const float* __restrict__ hb1, const float* __restrict__ hb2,
               const float* __restrict__ hb3, const float* __restrict__ bb1,
               const float* __restrict__ bb2, const float* __restrict__ bb3,
               const float* __restrict__ cb1, const float* __restrict__ cb2,
               const float* __restrict__ cb3,
               const float* __restrict__ pos_emb, const float* __restrict__ action_emb,
               const float* __restrict__ active_emb, const float* __restrict__ street_emb,
               const float* __restrict__ numpl_emb, const float* __restrict__ blind_emb,
               const float* __restrict__ scalar_W, const float* __restrict__ scalar_b,
               float* __restrict__ out)
{
    extern __shared__ float smem[];
    float* blob = smem + OFF_BLOB;
    float* sW   = smem + OFF_SW;
    float* sB   = smem + OFF_SB;
    float* bias = smem + OFF_BIAS;
    float* A    = smem + OFF_A;      // stride 84
    float* Bb   = smem + OFF_B;      // stride 84
    float* C    = smem + OFF_C;      // stride 148
    float* D    = smem + OFF_A;      // stride 148 (overlays A+B)
    float* W    = smem + OFF_W;

    const int t = threadIdx.x;
    const size_t g0 = (size_t)blockIdx.x * TROWS;
    const float* st = state + g0 * 50;

    // ---- stage tables + biases ----
    for (int i = t; i < 40;  i += NTHREADS) blob[0   + i] = suit_emb[i];
    for (int i = t; i < 112; i += NTHREADS) blob[40  + i] = rank_emb[i];
    for (int i = t; i < 56;  i += NTHREADS) blob[152 + i] = pos_emb[i];
    for (int i = t; i < 96;  i += NTHREADS) blob[208 + i] = action_emb[i];
    for (int i = t; i < 16;  i += NTHREADS) blob[304 + i] = active_emb[i];
    for (int i = t; i < 40;  i += NTHREADS) blob[320 + i] = street_emb[i];
    for (int i = t; i < 56;  i += NTHREADS) blob[360 + i] = numpl_emb[i];
    for (int i = t; i < 16;  i += NTHREADS) blob[416 + i] = blind_emb[i];
    for (int i = t; i < 48;  i += NTHREADS) { sW[i] = scalar_W[i]; sB[i] = scalar_b[i]; }
    for (int i = t; i < 64;  i += NTHREADS) bias[0   + i] = hb1[i];
    for (int i = t; i < 64;  i += NTHREADS) bias[64  + i] = hb2[i];
    for (int i = t; i < 64;  i += NTHREADS) bias[128 + i] = hb3[i];
    for (int i = t; i < 80;  i += NTHREADS) bias[192 + i] = bb1[i];
    for (int i = t; i < 80;  i += NTHREADS) bias[272 + i] = bb2[i];
    for (int i = t; i < 80;  i += NTHREADS) bias[352 + i] = bb3[i];
    for (int i = t; i < 144; i += NTHREADS) bias[432 + i] = cb1[i];
    for (int i = t; i < 64;  i += NTHREADS) bias[576 + i] = cb2[i];
    for (int i = t; i < 64;  i += NTHREADS) bias[640 + i] = cb3[i];
    __syncthreads();

    // ---- cheap output columns 64..311 ----
    for (int i = t; i < TROWS * 248; i += NTHREADS) {
        int r = i / 248, cc = i - r * 248;
        int ch = cc >> 3, e = cc & 7;
        int kind = c_kind[ch], Ai = c_A[ch], Bc = c_B[ch];
        float v;
        if (kind == 0) {
            int xi = (int)__ldg(st + r * 50 + Bc);
            v = blob[Ai + xi * 8 + e];
        } else {
            v = __ldg(st + r * 50 + Ai) * sW[Bc * 8 + e] + sB[Bc * 8 + e];
        }
        out[(g0 + r) * 312 + 64 + cc] = v;
    }

    // ---- gather hand input (64 feats) -> A row-major ----
    for (int i = t; i < 64 * TROWS; i += NTHREADS) {
        int r = i & 63, k = i >> 6;
        int c = k >> 4, w = k & 15;
        float v;
        if (w < 8) { int s  = (int)__ldg(st + r * 50 + 2 * c + 1); v = blob[0  + s * 8 + w]; }
        else       { int rk = (int)__ldg(st + r * 50 + 2 * c);     v = blob[40 + rk * 8 + (w - 8)]; }
        A[r * 84 + k] = v;
    }
    // (h1's prologue barrier establishes visibility)

    layer<64, 84, 64, 84,  0,  32, true >(A,  Bb, g_wt + 0,     bias + 0,   W);
    layer<64, 84, 64, 84,  0,  32, true >(Bb, A,  g_wt + 4096,  bias + 64,  W);
    layer<64, 84, 64, 148, 0,  32, false>(A,  C,  g_wt + 8192,  bias + 128, W);

    __syncthreads();  // h3 done reading A before board gather overwrites

    // ---- gather board input (80 feats) -> A ----
    for (int i = t; i < 80 * TROWS; i += NTHREADS) {
        int r = i & 63, k = i >> 6;
        int c = k >> 4, w = k & 15;
        float v;
        if (w < 8) { int s  = (int)__ldg(st + r * 50 + 9 + 2 * c); v = blob[0  + s * 8 + w]; }
        else       { int rk = (int)__ldg(st + r * 50 + 8 + 2 * c); v = blob[40 + rk * 8 + (w - 8)]; }
        A[r * 84 + k] = v;
    }

    layer<80, 84, 80, 84,  0,  40, true >(A,  Bb, g_wt + 12288, bias + 192, W);
    layer<80, 84, 80, 84,  0,  40, true >(Bb, A,  g_wt + 18688, bias + 272, W);
    layer<80, 84, 80, 148, 64, 40, false>(A,  C,  g_wt + 25088, bias + 352, W);

    // ---- combined MLP: C[144] -> D[144] -> C[0:64) -> out ----
    layer<144, 148, 80, 148, 0,  36, true>(C, D, g_wt + 31488,            bias + 432,      W);
    layer<144, 148, 64, 148, 80, 36, true>(C, D, g_wt + 31488 + 80 * 144, bias + 432 + 80, W);
    layer<144, 148, 64, 148, 0,  48, true>(D, C, g_wt + 52224,            bias + 576,      W);
    layer_final(C, g_wt + 61440, bias + 640, W, out, g0);
}

extern "C" void kernel_launch(void* const* d_in, const int* in_sizes, int n_in,
                              void* d_out, int out_size)
{
    (void)n_in; (void)out_size;
    cudaFuncSetAttribute(preproc_kernel, cudaFuncAttributeMaxDynamicSharedMemorySize, SMEM_BYTES);

    // one-time-per-graph weight transpose into g_wt
    prep_kernel<<<256, 256>>>(
        (const float*)d_in[3],  (const float*)d_in[5],  (const float*)d_in[7],
        (const float*)d_in[9],  (const float*)d_in[11], (const float*)d_in[13],
        (const float*)d_in[15], (const float*)d_in[17], (const float*)d_in[19]);

    const int nrows = in_sizes[0] / 50;     // 262144
    const int grid  = nrows / TROWS;        // 4096

    preproc_kernel<<<grid, NTHREADS, SMEM_BYTES>>>(
        (const float*)d_in[0],
        (const float*)d_in[1],  (const float*)d_in[2],
        (const float*)d_in[4],  (const float*)d_in[6],  (const float*)d_in[8],
        (const float*)d_in[10], (const float*)d_in[12], (const float*)d_in[14],
        (const float*)d_in[16], (const float*)d_in[18], (const float*)d_in[20],
        (const float*)d_in[21], (const float*)d_in[22],
        (const float*)d_in[23], (const float*)d_in[24],
        (const float*)d_in[25], (const float*)d_in[26],
        (const float*)d_in[27], (const float*)d_in[28],
        (float*)d_out);
}